// round 8
// baseline (speedup 1.0000x reference)
#include <cuda_runtime.h>
#include <cstdint>

// ---------------- scratch (no allocations allowed) ----------------
#define MAX_K      65536
#define MAX_BLOCKS 4096
#define CBS        256   // compaction block size

__device__ int g_idx[MAX_K];        // compacted masked node ids, in node order
__device__ int g_counts[MAX_BLOCKS];

// ---------------- pass 1: per-block masked count ----------------
__global__ void count_kernel(const int* __restrict__ sym, int N,
                             const int* __restrict__ symbuf, int T) {
    __shared__ int sbuf[8];
    __shared__ int warp_cnt[CBS / 32];
    int tid = threadIdx.x;
    if (tid < T && tid < 8) sbuf[tid] = symbuf[tid];
    __syncthreads();
    int i = blockIdx.x * CBS + tid;
    bool m = false;
    if (i < N) {
        int s = sym[i];
        #pragma unroll 4
        for (int t = 0; t < T; t++) m |= (s == sbuf[t]);
    }
    unsigned ball = __ballot_sync(0xffffffffu, m);
    if ((tid & 31) == 0) warp_cnt[tid >> 5] = __popc(ball);
    __syncthreads();
    if (tid == 0) {
        int c = 0;
        #pragma unroll
        for (int k = 0; k < CBS / 32; k++) c += warp_cnt[k];
        g_counts[blockIdx.x] = c;
    }
}

// ---------------- pass 2 (fused): per-block prefix recompute + ordered scatter ----------------
__global__ void scatter_fused_kernel(const int* __restrict__ sym, int N,
                                     const int* __restrict__ symbuf, int T) {
    __shared__ int sbuf[8];
    __shared__ int red[CBS / 32];
    __shared__ int warp_off[CBS / 32];
    __shared__ int block_pre;

    int tid = threadIdx.x;
    int b = blockIdx.x;
    if (tid < T && tid < 8) sbuf[tid] = symbuf[tid];

    int pre = 0;
    for (int j = tid; j < b; j += CBS) pre += g_counts[j];
    #pragma unroll
    for (int o = 16; o; o >>= 1) pre += __shfl_down_sync(0xffffffffu, pre, o);
    if ((tid & 31) == 0) red[tid >> 5] = pre;
    __syncthreads();
    if (tid == 0) {
        int s = 0;
        #pragma unroll
        for (int k = 0; k < CBS / 32; k++) s += red[k];
        block_pre = s;
    }
    __syncthreads();

    int i = b * CBS + tid;
    bool m = false;
    if (i < N) {
        int s = sym[i];
        #pragma unroll 4
        for (int t = 0; t < T; t++) m |= (s == sbuf[t]);
    }
    unsigned ball = __ballot_sync(0xffffffffu, m);
    int lane = tid & 31, w = tid >> 5;
    if (lane == 0) warp_off[w] = __popc(ball);
    __syncthreads();
    if (tid == 0) {
        int acc = 0;
        #pragma unroll
        for (int k = 0; k < CBS / 32; k++) { int c = warp_off[k]; warp_off[k] = acc; acc += c; }
    }
    __syncthreads();
    if (m) {
        int pos = block_pre + warp_off[w] + __popc(ball & ((1u << lane) - 1u));
        g_idx[pos] = i;
    }
}

// ---------------- main: TMA-fed pipelined gather-dot ----------------
#define P_STAGES        3
#define NODES_PER_STAGE 4
#define GD_THREADS      128

__device__ __forceinline__ float dot4(float4 a, float4 b) {
    return a.x * b.x + a.y * b.y + a.z * b.z + a.w * b.w;
}

__device__ __forceinline__ void mbar_init(uint32_t mb, unsigned cnt) {
    asm volatile("mbarrier.init.shared.b64 [%0], %1;" :: "r"(mb), "r"(cnt) : "memory");
}
__device__ __forceinline__ void mbar_expect_tx(uint32_t mb, unsigned bytes) {
    asm volatile("mbarrier.arrive.expect_tx.shared.b64 _, [%0], %1;" :: "r"(mb), "r"(bytes) : "memory");
}
__device__ __forceinline__ void mbar_wait_parity(uint32_t mb, unsigned ph) {
    asm volatile(
        "{\n\t"
        ".reg .pred P1;\n\t"
        "WAIT_%=:\n\t"
        "mbarrier.try_wait.parity.acquire.cta.shared::cta.b64 P1, [%0], %1, 0x989680;\n\t"
        "@P1 bra.uni DONE_%=;\n\t"
        "bra.uni WAIT_%=;\n\t"
        "DONE_%=:\n\t"
        "}"
        :: "r"(mb), "r"(ph) : "memory");
}
__device__ __forceinline__ void bulk_copy_g2s(uint32_t dst, const void* src,
                                              unsigned bytes, uint32_t mb) {
    asm volatile(
        "cp.async.bulk.shared::cluster.global.mbarrier::complete_tx::bytes [%0], [%1], %2, [%3];"
        :: "r"(dst), "l"(src), "r"(bytes), "r"(mb) : "memory");
}

extern __shared__ char dyn_smem[];

__global__ void __launch_bounds__(GD_THREADS) gatherdot_tma_kernel(
    const float* __restrict__ f00, const float* __restrict__ f01,
    const float* __restrict__ f10, const float* __restrict__ f11,
    const float* __restrict__ f20, const float* __restrict__ f21,
    const float* __restrict__ w0, const float* __restrict__ w1,
    const float* __restrict__ w2,
    const float* __restrict__ b0, const float* __restrict__ b1,
    const float* __restrict__ b2,
    const int* __restrict__ meta,
    float* __restrict__ out, int K, int d4, int chunk)
{
    const int rowBytes   = d4 * 16;                         // bytes per feature row
    const int stageBytes = NODES_PER_STAGE * 6 * rowBytes;  // bytes per pipeline slot

    uint32_t smem_u32 = (uint32_t)__cvta_generic_to_shared(dyn_smem);
    uint32_t mbar0    = smem_u32;            // 3 mbarriers @ 0,8,16
    uint32_t data_u32 = smem_u32 + 128;
    char*    data     = dyn_smem + 128;

    int base = blockIdx.x * chunk;
    if (base >= K) return;
    int end = base + chunk; if (end > K) end = K;
    int nst = (end - base + NODES_PER_STAGE - 1) / NODES_PER_STAGE;

    int tid = threadIdx.x;
    if (tid == 0) {
        #pragma unroll
        for (int s = 0; s < P_STAGES; s++) mbar_init(mbar0 + 8u * s, 1);
    }
    __syncthreads();

    const float* farr0 = f00; const float* farr1 = f01;
    const float* farr2 = f10; const float* farr3 = f11;
    const float* farr4 = f20; const float* farr5 = f21;

    // ---- prologue: fill up to P_STAGES slots ----
    if (tid == 0) {
        int pmax = nst < P_STAGES ? nst : P_STAGES;
        for (int ls = 0; ls < pmax; ls++) {
            int s0 = base + ls * NODES_PER_STAGE;
            int vn = end - s0; if (vn > NODES_PER_STAGE) vn = NODES_PER_STAGE;
            uint32_t mb = mbar0 + 8u * ls;
            mbar_expect_tx(mb, (unsigned)(vn * 6 * rowBytes));
            for (int nn = 0; nn < vn; nn++) {
                size_t roff = (size_t)g_idx[s0 + nn] * (size_t)rowBytes;
                uint32_t d = data_u32 + ls * stageBytes + nn * 6 * rowBytes;
                bulk_copy_g2s(d + 0 * rowBytes, (const char*)farr0 + roff, rowBytes, mb);
                bulk_copy_g2s(d + 1 * rowBytes, (const char*)farr1 + roff, rowBytes, mb);
                bulk_copy_g2s(d + 2 * rowBytes, (const char*)farr2 + roff, rowBytes, mb);
                bulk_copy_g2s(d + 3 * rowBytes, (const char*)farr3 + roff, rowBytes, mb);
                bulk_copy_g2s(d + 4 * rowBytes, (const char*)farr4 + roff, rowBytes, mb);
                bulk_copy_g2s(d + 5 * rowBytes, (const char*)farr5 + roff, rowBytes, mb);
            }
        }
    }

    int lane = tid & 31, w = tid >> 5;

    for (int ls = 0; ls < nst; ls++) {
        int slot = ls % P_STAGES;
        unsigned ph = (unsigned)((ls / P_STAGES) & 1);
        mbar_wait_parity(mbar0 + 8u * slot, ph);

        int n = base + ls * NODES_PER_STAGE + w;
        if (n < end) {
            int i   = g_idx[n];
            int mid = meta[i];
            size_t wo = (size_t)mid * (size_t)d4;
            float bias = 2.0f * (b0[mid] + b1[mid] + b2[mid]);

            const float4* rows = (const float4*)(data + slot * stageBytes + w * 6 * rowBytes);
            const float4* W0 = (const float4*)w0;
            const float4* W1 = (const float4*)w1;
            const float4* W2 = (const float4*)w2;

            float acc = 0.0f;
            #pragma unroll 2
            for (int c = lane; c < d4; c += 32) {
                float4 a0 = W0[wo + c];
                float4 a1 = W1[wo + c];
                float4 a2 = W2[wo + c];
                float4 x;
                x = rows[0 * d4 + c]; acc += dot4(x, a0);
                x = rows[1 * d4 + c]; acc += dot4(x, a0);
                x = rows[2 * d4 + c]; acc += dot4(x, a1);
                x = rows[3 * d4 + c]; acc += dot4(x, a1);
                x = rows[4 * d4 + c]; acc += dot4(x, a2);
                x = rows[5 * d4 + c]; acc += dot4(x, a2);
            }
            #pragma unroll
            for (int off = 16; off; off >>= 1)
                acc += __shfl_down_sync(0xffffffffu, acc, off);
            if (lane == 0) out[n] = (acc + bias) * (1.0f / 6.0f);
        }

        __syncthreads();   // all warps done reading slot before re-arm/refill

        int np = ls + P_STAGES;
        if (tid == 0 && np < nst) {
            int s0 = base + np * NODES_PER_STAGE;
            int vn = end - s0; if (vn > NODES_PER_STAGE) vn = NODES_PER_STAGE;
            uint32_t mb = mbar0 + 8u * slot;
            mbar_expect_tx(mb, (unsigned)(vn * 6 * rowBytes));
            for (int nn = 0; nn < vn; nn++) {
                size_t roff = (size_t)g_idx[s0 + nn] * (size_t)rowBytes;
                uint32_t d = data_u32 + slot * stageBytes + nn * 6 * rowBytes;
                bulk_copy_g2s(d + 0 * rowBytes, (const char*)farr0 + roff, rowBytes, mb);
                bulk_copy_g2s(d + 1 * rowBytes, (const char*)farr1 + roff, rowBytes, mb);
                bulk_copy_g2s(d + 2 * rowBytes, (const char*)farr2 + roff, rowBytes, mb);
                bulk_copy_g2s(d + 3 * rowBytes, (const char*)farr3 + roff, rowBytes, mb);
                bulk_copy_g2s(d + 4 * rowBytes, (const char*)farr4 + roff, rowBytes, mb);
                bulk_copy_g2s(d + 5 * rowBytes, (const char*)farr5 + roff, rowBytes, mb);
            }
        }
    }
}

// ---------------- launcher ----------------
extern "C" void kernel_launch(void* const* d_in, const int* in_sizes, int n_in,
                              void* d_out, int out_size) {
    const float* f00 = (const float*)d_in[0];
    const float* f01 = (const float*)d_in[1];
    const float* f10 = (const float*)d_in[2];
    const float* f11 = (const float*)d_in[3];
    const float* f20 = (const float*)d_in[4];
    const float* f21 = (const float*)d_in[5];
    const float* w0  = (const float*)d_in[6];
    const float* w1  = (const float*)d_in[7];
    const float* w2  = (const float*)d_in[8];
    const float* b0  = (const float*)d_in[9];
    const float* b1  = (const float*)d_in[10];
    const float* b2  = (const float*)d_in[11];
    const int* symbols = (const int*)d_in[12];
    const int* meta    = (const int*)d_in[13];
    const int* sym_buf = (const int*)d_in[14];

    int M = in_sizes[9];                 // b0 has M elements
    int D = in_sizes[6] / M;             // w0 has M*D
    int N = in_sizes[0] / D;             // feat00 has N*D
    int T = in_sizes[14];                // sym_buf length
    int K = out_size;                    // masked count
    (void)n_in;

    int nb = (N + CBS - 1) / CBS;

    count_kernel<<<nb, CBS>>>(symbols, N, sym_buf, T);
    scatter_fused_kernel<<<nb, CBS>>>(symbols, N, sym_buf, T);

    int rowBytes = D * 4;
    int smemBytes = 128 + P_STAGES * NODES_PER_STAGE * 6 * rowBytes;  // 73856 for D=256

    static int attr_done = 0;
    if (!attr_done) {
        cudaFuncSetAttribute(gatherdot_tma_kernel,
                             cudaFuncAttributeMaxDynamicSharedMemorySize, 232448);
        attr_done = 1;
    }

    int blocks = 444;                                  // ~3 blocks/SM
    int maxBlocks = (K + NODES_PER_STAGE - 1) / NODES_PER_STAGE;
    if (blocks > maxBlocks) blocks = maxBlocks;
    int chunk = (K + blocks - 1) / blocks;
    chunk = (chunk + NODES_PER_STAGE - 1) & ~(NODES_PER_STAGE - 1);

    gatherdot_tma_kernel<<<blocks, GD_THREADS, smemBytes>>>(
        f00, f01, f10, f11, f20, f21,
        w0, w1, w2, b0, b1, b2,
        meta, (float*)d_out, K, D / 4, chunk);
}

// round 9
// speedup vs baseline: 1.2428x; 1.2428x over previous
#include <cuda_runtime.h>
#include <cstdint>

// ---------------- scratch (no allocations allowed) ----------------
#define MAX_K      65536
#define MAX_BLOCKS 4096
#define CBS        256   // compaction block size

__device__ int g_idx[MAX_K];        // compacted masked node ids, in node order
__device__ int g_counts[MAX_BLOCKS];

// ---------------- pass 1: per-block masked count ----------------
__global__ void count_kernel(const int* __restrict__ sym, int N,
                             const int* __restrict__ symbuf, int T) {
    __shared__ int sbuf[8];
    __shared__ int warp_cnt[CBS / 32];
    int tid = threadIdx.x;
    if (tid < T && tid < 8) sbuf[tid] = symbuf[tid];
    __syncthreads();
    int i = blockIdx.x * CBS + tid;
    bool m = false;
    if (i < N) {
        int s = sym[i];
        #pragma unroll 4
        for (int t = 0; t < T; t++) m |= (s == sbuf[t]);
    }
    unsigned ball = __ballot_sync(0xffffffffu, m);
    if ((tid & 31) == 0) warp_cnt[tid >> 5] = __popc(ball);
    __syncthreads();
    if (tid == 0) {
        int c = 0;
        #pragma unroll
        for (int k = 0; k < CBS / 32; k++) c += warp_cnt[k];
        g_counts[blockIdx.x] = c;
    }
}

// ---------------- pass 2 (fused): per-block prefix recompute + ordered scatter ----------------
__global__ void scatter_fused_kernel(const int* __restrict__ sym, int N,
                                     const int* __restrict__ symbuf, int T) {
    __shared__ int sbuf[8];
    __shared__ int red[CBS / 32];
    __shared__ int warp_off[CBS / 32];
    __shared__ int block_pre;

    int tid = threadIdx.x;
    int b = blockIdx.x;
    if (tid < T && tid < 8) sbuf[tid] = symbuf[tid];

    int pre = 0;
    for (int j = tid; j < b; j += CBS) pre += g_counts[j];
    #pragma unroll
    for (int o = 16; o; o >>= 1) pre += __shfl_down_sync(0xffffffffu, pre, o);
    if ((tid & 31) == 0) red[tid >> 5] = pre;
    __syncthreads();
    if (tid == 0) {
        int s = 0;
        #pragma unroll
        for (int k = 0; k < CBS / 32; k++) s += red[k];
        block_pre = s;
    }
    __syncthreads();

    int i = b * CBS + tid;
    bool m = false;
    if (i < N) {
        int s = sym[i];
        #pragma unroll 4
        for (int t = 0; t < T; t++) m |= (s == sbuf[t]);
    }
    unsigned ball = __ballot_sync(0xffffffffu, m);
    int lane = tid & 31, w = tid >> 5;
    if (lane == 0) warp_off[w] = __popc(ball);
    __syncthreads();
    if (tid == 0) {
        int acc = 0;
        #pragma unroll
        for (int k = 0; k < CBS / 32; k++) { int c = warp_off[k]; warp_off[k] = acc; acc += c; }
    }
    __syncthreads();
    if (m) {
        int pos = block_pre + warp_off[w] + __popc(ball & ((1u << lane) - 1u));
        g_idx[pos] = i;
    }
}

// ---------------- main: persistent gather-dot + L2 bulk-prefetch of next node ----------------
__device__ __forceinline__ float dot4(float4 a, float4 b) {
    return a.x * b.x + a.y * b.y + a.z * b.z + a.w * b.w;
}

__device__ __forceinline__ void prefetch_l2(const void* p, unsigned bytes) {
    asm volatile("cp.async.bulk.prefetch.L2.global [%0], %1;" :: "l"(p), "r"(bytes));
}

__global__ void __launch_bounds__(256, 8) gatherdot_kernel(
    const float* __restrict__ f00, const float* __restrict__ f01,
    const float* __restrict__ f10, const float* __restrict__ f11,
    const float* __restrict__ f20, const float* __restrict__ f21,
    const float* __restrict__ w0, const float* __restrict__ w1,
    const float* __restrict__ w2,
    const float* __restrict__ b0, const float* __restrict__ b1,
    const float* __restrict__ b2,
    const int* __restrict__ meta,
    float* __restrict__ out, int K, int d4)
{
    int lane = threadIdx.x & 31;
    int warp0 = (blockIdx.x * blockDim.x + threadIdx.x) >> 5;
    int nwarps = (gridDim.x * blockDim.x) >> 5;
    unsigned rowBytes = (unsigned)(d4 * 16);

    for (int gw = warp0; gw < K; gw += nwarps) {
        // ---- prefetch NEXT node's 6 feature rows into L2 (bulk queue, no MSHR) ----
        int nx = gw + nwarps;
        if (nx < K && lane < 6) {
            size_t roff = (size_t)g_idx[nx] * (size_t)rowBytes;
            const float* arr =
                (lane == 0) ? f00 : (lane == 1) ? f01 :
                (lane == 2) ? f10 : (lane == 3) ? f11 :
                (lane == 4) ? f20 : f21;
            prefetch_l2((const char*)arr + roff, rowBytes);
        }

        int i = g_idx[gw];
        int mid = meta[i];

        size_t fo = (size_t)i * (size_t)d4;
        size_t wo = (size_t)mid * (size_t)d4;

        // independent bias loads issued early (L2-resident, tiny)
        float bias = 2.0f * (b0[mid] + b1[mid] + b2[mid]);

        float acc = 0.0f;

        #pragma unroll 3
        for (int p = 0; p < 3; p++) {
            const float4* W;
            const float4* Fa;
            const float4* Fb;
            if (p == 0)      { W = (const float4*)w0; Fa = (const float4*)f00; Fb = (const float4*)f01; }
            else if (p == 1) { W = (const float4*)w1; Fa = (const float4*)f10; Fb = (const float4*)f11; }
            else             { W = (const float4*)w2; Fa = (const float4*)f20; Fb = (const float4*)f21; }

            #pragma unroll 2
            for (int c = lane; c < d4; c += 32) {
                float4 a  = W[wo + c];               // L2-cached (heavy reuse across nodes)
                float4 x0 = __ldcs(&Fa[fo + c]);     // streamed; L2-hit after prefetch
                float4 x1 = __ldcs(&Fb[fo + c]);
                acc += dot4(x0, a) + dot4(x1, a);
            }
        }

        // warp reduction
        #pragma unroll
        for (int off = 16; off; off >>= 1)
            acc += __shfl_down_sync(0xffffffffu, acc, off);

        if (lane == 0) {
            out[gw] = (acc + bias) * (1.0f / 6.0f);
        }
    }
}

// ---------------- launcher ----------------
extern "C" void kernel_launch(void* const* d_in, const int* in_sizes, int n_in,
                              void* d_out, int out_size) {
    const float* f00 = (const float*)d_in[0];
    const float* f01 = (const float*)d_in[1];
    const float* f10 = (const float*)d_in[2];
    const float* f11 = (const float*)d_in[3];
    const float* f20 = (const float*)d_in[4];
    const float* f21 = (const float*)d_in[5];
    const float* w0  = (const float*)d_in[6];
    const float* w1  = (const float*)d_in[7];
    const float* w2  = (const float*)d_in[8];
    const float* b0  = (const float*)d_in[9];
    const float* b1  = (const float*)d_in[10];
    const float* b2  = (const float*)d_in[11];
    const int* symbols = (const int*)d_in[12];
    const int* meta    = (const int*)d_in[13];
    const int* sym_buf = (const int*)d_in[14];

    int M = in_sizes[9];                 // b0 has M elements
    int D = in_sizes[6] / M;             // w0 has M*D
    int N = in_sizes[0] / D;             // feat00 has N*D
    int T = in_sizes[14];                // sym_buf length
    int K = out_size;                    // masked count
    (void)M; (void)n_in;

    int nb = (N + CBS - 1) / CBS;        // 782 for N=200000 (< MAX_BLOCKS)

    count_kernel<<<nb, CBS>>>(symbols, N, sym_buf, T);
    scatter_fused_kernel<<<nb, CBS>>>(symbols, N, sym_buf, T);

    // persistent launch: one full wave (148 SMs x 8 blocks), each warp ~5 nodes,
    // giving the L2 prefetch one-node lookahead distance.
    int blocks = 1184;
    int maxBlocks = (K + 7) / 8;
    if (blocks > maxBlocks) blocks = maxBlocks;
    gatherdot_kernel<<<blocks, 256>>>(
        f00, f01, f10, f11, f20, f21,
        w0, w1, w2, b0, b1, b2,
        meta, (float*)d_out, K, D / 4);
}

// round 10
// speedup vs baseline: 1.2573x; 1.0117x over previous
#include <cuda_runtime.h>
#include <cstdint>

// ---------------- scratch (no allocations allowed) ----------------
#define MAX_K      65536
#define MAX_BLOCKS 4096
#define CBS        256   // compaction block size

__device__ int g_idx[MAX_K];        // compacted masked node ids, in node order
__device__ int g_counts[MAX_BLOCKS];

// ---------------- pass 1: per-block masked count ----------------
__global__ void count_kernel(const int* __restrict__ sym, int N,
                             const int* __restrict__ symbuf, int T) {
    __shared__ int sbuf[8];
    __shared__ int warp_cnt[CBS / 32];
    int tid = threadIdx.x;
    if (tid < T && tid < 8) sbuf[tid] = symbuf[tid];
    __syncthreads();
    int i = blockIdx.x * CBS + tid;
    bool m = false;
    if (i < N) {
        int s = sym[i];
        #pragma unroll 4
        for (int t = 0; t < T; t++) m |= (s == sbuf[t]);
    }
    unsigned ball = __ballot_sync(0xffffffffu, m);
    if ((tid & 31) == 0) warp_cnt[tid >> 5] = __popc(ball);
    __syncthreads();
    if (tid == 0) {
        int c = 0;
        #pragma unroll
        for (int k = 0; k < CBS / 32; k++) c += warp_cnt[k];
        g_counts[blockIdx.x] = c;
    }
}

// ---------------- pass 2 (fused): per-block prefix recompute + ordered scatter ----------------
__global__ void scatter_fused_kernel(const int* __restrict__ sym, int N,
                                     const int* __restrict__ symbuf, int T) {
    __shared__ int sbuf[8];
    __shared__ int red[CBS / 32];
    __shared__ int warp_off[CBS / 32];
    __shared__ int block_pre;

    int tid = threadIdx.x;
    int b = blockIdx.x;
    if (tid < T && tid < 8) sbuf[tid] = symbuf[tid];

    int pre = 0;
    for (int j = tid; j < b; j += CBS) pre += g_counts[j];
    #pragma unroll
    for (int o = 16; o; o >>= 1) pre += __shfl_down_sync(0xffffffffu, pre, o);
    if ((tid & 31) == 0) red[tid >> 5] = pre;
    __syncthreads();
    if (tid == 0) {
        int s = 0;
        #pragma unroll
        for (int k = 0; k < CBS / 32; k++) s += red[k];
        block_pre = s;
    }
    __syncthreads();

    int i = b * CBS + tid;
    bool m = false;
    if (i < N) {
        int s = sym[i];
        #pragma unroll 4
        for (int t = 0; t < T; t++) m |= (s == sbuf[t]);
    }
    unsigned ball = __ballot_sync(0xffffffffu, m);
    int lane = tid & 31, w = tid >> 5;
    if (lane == 0) warp_off[w] = __popc(ball);
    __syncthreads();
    if (tid == 0) {
        int acc = 0;
        #pragma unroll
        for (int k = 0; k < CBS / 32; k++) { int c = warp_off[k]; warp_off[k] = acc; acc += c; }
    }
    __syncthreads();
    if (m) {
        int pos = block_pre + warp_off[w] + __popc(ball & ((1u << lane) - 1u));
        g_idx[pos] = i;
    }
}

// ---------------- cp.async helpers ----------------
__device__ __forceinline__ void cp16(uint32_t dst, const void* src) {
    asm volatile("cp.async.cg.shared.global [%0], [%1], 16;"
                 :: "r"(dst), "l"(src) : "memory");
}
__device__ __forceinline__ void cp_commit() {
    asm volatile("cp.async.commit_group;" ::: "memory");
}
template<int N>
__device__ __forceinline__ void cp_wait() {
    asm volatile("cp.async.wait_group %0;" :: "n"(N) : "memory");
}

__device__ __forceinline__ float dot4(float4 a, float4 b) {
    return a.x * b.x + a.y * b.y + a.z * b.z + a.w * b.w;
}

// ---------------- main: per-warp cp.async-pipelined gather-dot (d4==64) ----------------
#define GD_WARPS 8
#define SLOTS    6   // one 1KB slot per feature row of a node; ring reuse across nodes
#define AHEAD    5

__global__ void __launch_bounds__(256, 4) gatherdot_pipe_kernel(
    const float* __restrict__ f00, const float* __restrict__ f01,
    const float* __restrict__ f10, const float* __restrict__ f11,
    const float* __restrict__ f20, const float* __restrict__ f21,
    const float* __restrict__ w0, const float* __restrict__ w1,
    const float* __restrict__ w2,
    const float* __restrict__ b0, const float* __restrict__ b1,
    const float* __restrict__ b2,
    const int* __restrict__ meta,
    float* __restrict__ out, int K)
{
    __shared__ float4 buf[GD_WARPS][SLOTS][64];   // 8 * 6 * 1KB = 48KB

    const int d4 = 64;
    int lane = threadIdx.x & 31;
    int w = threadIdx.x >> 5;
    int warp0 = blockIdx.x * GD_WARPS + w;
    int nwarps = gridDim.x * GD_WARPS;

    int nNodes = (warp0 < K) ? ((K - 1 - warp0) / nwarps + 1) : 0;
    int totalRows = nNodes * 6;
    if (totalRows == 0) return;

    uint32_t bufBase = (uint32_t)__cvta_generic_to_shared(&buf[w][0][0]);

    const float4* W0 = (const float4*)w0;
    const float4* W1 = (const float4*)w1;
    const float4* W2 = (const float4*)w2;

    // issue-side counters
    int iNode = 0, iR = 0;
    // consume-side state
    int cNode = 0, cR = 0;
    size_t wo = 0; float bias = 0.0f, acc = 0.0f;

    // issue row (iNode, iR) then advance
    auto issue = [&]() {
        int gw = warp0 + iNode * nwarps;
        int i = g_idx[gw];
        const float* arr;
        switch (iR) {
            case 0: arr = f00; break;
            case 1: arr = f01; break;
            case 2: arr = f10; break;
            case 3: arr = f11; break;
            case 4: arr = f20; break;
            default: arr = f21; break;
        }
        int slot = iR;                                  // SLOTS==6 -> slot = row index
        const char* src = (const char*)arr + ((size_t)i * 1024u) + (unsigned)(lane * 16);
        uint32_t dst = bufBase + (uint32_t)(slot * 1024 + lane * 16);
        cp16(dst, src);
        cp16(dst + 512u, src + 512);
        cp_commit();
        if (++iR == 6) { iR = 0; ++iNode; }
    };

    // prologue: AHEAD rows in flight
    int pro = totalRows < AHEAD ? totalRows : AHEAD;
    for (int j = 0; j < pro; j++) issue();

    int issued = pro;
    for (int j = 0; j < totalRows; j++) {
        if (issued < totalRows) { issue(); ++issued; }
        cp_wait<AHEAD>();                               // row j complete (each lane reads own copies)

        int r = cR;
        if (r == 0) {
            int gw = warp0 + cNode * nwarps;
            int i = g_idx[gw];
            int mid = meta[i];
            wo = (size_t)mid * (size_t)d4;
            bias = 2.0f * (b0[mid] + b1[mid] + b2[mid]);
            acc = 0.0f;
        }

        float4 x0 = buf[w][r][lane];
        float4 x1 = buf[w][r][lane + 32];
        const float4* W = (r < 2) ? W0 : (r < 4) ? W1 : W2;
        float4 a0 = W[wo + lane];
        float4 a1 = W[wo + lane + 32];
        acc += dot4(x0, a0) + dot4(x1, a1);

        if (r == 5) {
            float s = acc;
            #pragma unroll
            for (int off = 16; off; off >>= 1)
                s += __shfl_down_sync(0xffffffffu, s, off);
            if (lane == 0)
                out[warp0 + cNode * nwarps] = (s + bias) * (1.0f / 6.0f);
            cR = 0; ++cNode;
        } else {
            ++cR;
        }
    }
}

// ---------------- fallback: proven R4-style kernel for d4 != 64 ----------------
__global__ void __launch_bounds__(256, 8) gatherdot_kernel(
    const float* __restrict__ f00, const float* __restrict__ f01,
    const float* __restrict__ f10, const float* __restrict__ f11,
    const float* __restrict__ f20, const float* __restrict__ f21,
    const float* __restrict__ w0, const float* __restrict__ w1,
    const float* __restrict__ w2,
    const float* __restrict__ b0, const float* __restrict__ b1,
    const float* __restrict__ b2,
    const int* __restrict__ meta,
    float* __restrict__ out, int K, int d4)
{
    int gw = (blockIdx.x * blockDim.x + threadIdx.x) >> 5;
    if (gw >= K) return;
    int lane = threadIdx.x & 31;

    int i = g_idx[gw];
    int mid = meta[i];
    size_t fo = (size_t)i * (size_t)d4;
    size_t wo = (size_t)mid * (size_t)d4;
    float bias = 2.0f * (b0[mid] + b1[mid] + b2[mid]);
    float acc = 0.0f;

    #pragma unroll 3
    for (int p = 0; p < 3; p++) {
        const float4* W; const float4* Fa; const float4* Fb;
        if (p == 0)      { W = (const float4*)w0; Fa = (const float4*)f00; Fb = (const float4*)f01; }
        else if (p == 1) { W = (const float4*)w1; Fa = (const float4*)f10; Fb = (const float4*)f11; }
        else             { W = (const float4*)w2; Fa = (const float4*)f20; Fb = (const float4*)f21; }
        for (int c = lane; c < d4; c += 32) {
            float4 a  = W[wo + c];
            float4 x0 = __ldcs(&Fa[fo + c]);
            float4 x1 = __ldcs(&Fb[fo + c]);
            acc += dot4(x0, a) + dot4(x1, a);
        }
    }
    #pragma unroll
    for (int off = 16; off; off >>= 1)
        acc += __shfl_down_sync(0xffffffffu, acc, off);
    if (lane == 0) out[gw] = (acc + bias) * (1.0f / 6.0f);
}

// ---------------- launcher ----------------
extern "C" void kernel_launch(void* const* d_in, const int* in_sizes, int n_in,
                              void* d_out, int out_size) {
    const float* f00 = (const float*)d_in[0];
    const float* f01 = (const float*)d_in[1];
    const float* f10 = (const float*)d_in[2];
    const float* f11 = (const float*)d_in[3];
    const float* f20 = (const float*)d_in[4];
    const float* f21 = (const float*)d_in[5];
    const float* w0  = (const float*)d_in[6];
    const float* w1  = (const float*)d_in[7];
    const float* w2  = (const float*)d_in[8];
    const float* b0  = (const float*)d_in[9];
    const float* b1  = (const float*)d_in[10];
    const float* b2  = (const float*)d_in[11];
    const int* symbols = (const int*)d_in[12];
    const int* meta    = (const int*)d_in[13];
    const int* sym_buf = (const int*)d_in[14];

    int M = in_sizes[9];                 // b0 has M elements
    int D = in_sizes[6] / M;             // w0 has M*D
    int N = in_sizes[0] / D;             // feat00 has N*D
    int T = in_sizes[14];                // sym_buf length
    int K = out_size;                    // masked count
    (void)M; (void)n_in;

    int nb = (N + CBS - 1) / CBS;

    count_kernel<<<nb, CBS>>>(symbols, N, sym_buf, T);
    scatter_fused_kernel<<<nb, CBS>>>(symbols, N, sym_buf, T);

    if (D == 256) {
        // persistent: 148 SMs x 4 blocks (48KB smem each), 8 warps/block
        int blocks = 592;
        int maxBlocks = (K + GD_WARPS - 1) / GD_WARPS;
        if (blocks > maxBlocks) blocks = maxBlocks;
        gatherdot_pipe_kernel<<<blocks, 256>>>(
            f00, f01, f10, f11, f20, f21,
            w0, w1, w2, b0, b1, b2,
            meta, (float*)d_out, K);
    } else {
        int blocks = (K + 7) / 8;
        gatherdot_kernel<<<blocks, 256>>>(
            f00, f01, f10, f11, f20, f21,
            w0, w1, w2, b0, b1, b2,
            meta, (float*)d_out, K, D / 4);
    }
}

// round 11
// speedup vs baseline: 1.2779x; 1.0164x over previous
#include <cuda_runtime.h>

// ---------------- scratch (no allocations allowed) ----------------
#define MAX_K      65536
#define MAX_BLOCKS 4096
#define CBS        256   // compaction block size

__device__ int g_idx[MAX_K];        // compacted masked node ids, in node order
__device__ int g_counts[MAX_BLOCKS];

// ---------------- pass 1: per-block masked count ----------------
__global__ void count_kernel(const int* __restrict__ sym, int N,
                             const int* __restrict__ symbuf, int T) {
    __shared__ int sbuf[8];
    __shared__ int warp_cnt[CBS / 32];
    int tid = threadIdx.x;
    if (tid < T && tid < 8) sbuf[tid] = symbuf[tid];
    __syncthreads();
    int i = blockIdx.x * CBS + tid;
    bool m = false;
    if (i < N) {
        int s = sym[i];
        #pragma unroll 4
        for (int t = 0; t < T; t++) m |= (s == sbuf[t]);
    }
    unsigned ball = __ballot_sync(0xffffffffu, m);
    if ((tid & 31) == 0) warp_cnt[tid >> 5] = __popc(ball);
    __syncthreads();
    if (tid == 0) {
        int c = 0;
        #pragma unroll
        for (int k = 0; k < CBS / 32; k++) c += warp_cnt[k];
        g_counts[blockIdx.x] = c;
    }
}

// ---------------- pass 2 (fused): per-block prefix recompute + ordered scatter ----------------
__global__ void scatter_fused_kernel(const int* __restrict__ sym, int N,
                                     const int* __restrict__ symbuf, int T) {
    __shared__ int sbuf[8];
    __shared__ int red[CBS / 32];
    __shared__ int warp_off[CBS / 32];
    __shared__ int block_pre;

    int tid = threadIdx.x;
    int b = blockIdx.x;
    if (tid < T && tid < 8) sbuf[tid] = symbuf[tid];

    int pre = 0;
    for (int j = tid; j < b; j += CBS) pre += g_counts[j];
    #pragma unroll
    for (int o = 16; o; o >>= 1) pre += __shfl_down_sync(0xffffffffu, pre, o);
    if ((tid & 31) == 0) red[tid >> 5] = pre;
    __syncthreads();
    if (tid == 0) {
        int s = 0;
        #pragma unroll
        for (int k = 0; k < CBS / 32; k++) s += red[k];
        block_pre = s;
    }
    __syncthreads();

    int i = b * CBS + tid;
    bool m = false;
    if (i < N) {
        int s = sym[i];
        #pragma unroll 4
        for (int t = 0; t < T; t++) m |= (s == sbuf[t]);
    }
    unsigned ball = __ballot_sync(0xffffffffu, m);
    int lane = tid & 31, w = tid >> 5;
    if (lane == 0) warp_off[w] = __popc(ball);
    __syncthreads();
    if (tid == 0) {
        int acc = 0;
        #pragma unroll
        for (int k = 0; k < CBS / 32; k++) { int c = warp_off[k]; warp_off[k] = acc; acc += c; }
    }
    __syncthreads();
    if (m) {
        int pos = block_pre + warp_off[w] + __popc(ball & ((1u << lane) - 1u));
        g_idx[pos] = i;
    }
}

// ---------------- main: warp-per-2-nodes gather-dot (2KB-contiguous bursts) ----------------
__device__ __forceinline__ float dot4(float4 a, float4 b) {
    return a.x * b.x + a.y * b.y + a.z * b.z + a.w * b.w;
}

__global__ void __launch_bounds__(256, 5) gatherdot_kernel(
    const float* __restrict__ f00, const float* __restrict__ f01,
    const float* __restrict__ f10, const float* __restrict__ f11,
    const float* __restrict__ f20, const float* __restrict__ f21,
    const float* __restrict__ w0, const float* __restrict__ w1,
    const float* __restrict__ w2,
    const float* __restrict__ b0, const float* __restrict__ b1,
    const float* __restrict__ b2,
    const int* __restrict__ meta,
    float* __restrict__ out, int K, int d4)
{
    int gw2 = (blockIdx.x * blockDim.x + threadIdx.x) >> 5;   // warp handles nodes 2*gw2, 2*gw2+1
    int n0 = 2 * gw2;
    if (n0 >= K) return;
    int lane = threadIdx.x & 31;
    bool has1 = (n0 + 1) < K;

    int i0 = g_idx[n0];
    int i1 = has1 ? g_idx[n0 + 1] : i0;     // adjacent ranks -> (usually) adjacent rows
    int mid0 = meta[i0];
    int mid1 = meta[i1];

    size_t fo0 = (size_t)i0 * (size_t)d4;
    size_t fo1 = (size_t)i1 * (size_t)d4;
    size_t wo0 = (size_t)mid0 * (size_t)d4;
    size_t wo1 = (size_t)mid1 * (size_t)d4;

    float bias0 = 2.0f * (b0[mid0] + b1[mid0] + b2[mid0]);
    float bias1 = 2.0f * (b0[mid1] + b1[mid1] + b2[mid1]);

    float acc0 = 0.0f, acc1 = 0.0f;

    #pragma unroll 3
    for (int p = 0; p < 3; p++) {
        const float4* W;
        const float4* Fa;
        const float4* Fb;
        if (p == 0)      { W = (const float4*)w0; Fa = (const float4*)f00; Fb = (const float4*)f01; }
        else if (p == 1) { W = (const float4*)w1; Fa = (const float4*)f10; Fb = (const float4*)f11; }
        else             { W = (const float4*)w2; Fa = (const float4*)f20; Fb = (const float4*)f21; }

        #pragma unroll 2
        for (int c = lane; c < d4; c += 32) {
            float4 a0 = W[wo0 + c];               // L2-cached (heavy reuse across nodes)
            float4 a1 = W[wo1 + c];
            // feature bursts: rows i0 and i1 are adjacent -> 2KB-contiguous per array
            float4 x0 = __ldcs(&Fa[fo0 + c]);
            float4 x1 = __ldcs(&Fa[fo1 + c]);
            float4 y0 = __ldcs(&Fb[fo0 + c]);
            float4 y1 = __ldcs(&Fb[fo1 + c]);
            acc0 += dot4(x0, a0) + dot4(y0, a0);
            acc1 += dot4(x1, a1) + dot4(y1, a1);
        }
    }

    // warp reductions
    #pragma unroll
    for (int off = 16; off; off >>= 1) {
        acc0 += __shfl_down_sync(0xffffffffu, acc0, off);
        acc1 += __shfl_down_sync(0xffffffffu, acc1, off);
    }

    if (lane == 0) {
        out[n0] = (acc0 + bias0) * (1.0f / 6.0f);
        if (has1) out[n0 + 1] = (acc1 + bias1) * (1.0f / 6.0f);
    }
}

// ---------------- launcher ----------------
extern "C" void kernel_launch(void* const* d_in, const int* in_sizes, int n_in,
                              void* d_out, int out_size) {
    const float* f00 = (const float*)d_in[0];
    const float* f01 = (const float*)d_in[1];
    const float* f10 = (const float*)d_in[2];
    const float* f11 = (const float*)d_in[3];
    const float* f20 = (const float*)d_in[4];
    const float* f21 = (const float*)d_in[5];
    const float* w0  = (const float*)d_in[6];
    const float* w1  = (const float*)d_in[7];
    const float* w2  = (const float*)d_in[8];
    const float* b0  = (const float*)d_in[9];
    const float* b1  = (const float*)d_in[10];
    const float* b2  = (const float*)d_in[11];
    const int* symbols = (const int*)d_in[12];
    const int* meta    = (const int*)d_in[13];
    const int* sym_buf = (const int*)d_in[14];

    int M = in_sizes[9];                 // b0 has M elements
    int D = in_sizes[6] / M;             // w0 has M*D
    int N = in_sizes[0] / D;             // feat00 has N*D
    int T = in_sizes[14];                // sym_buf length
    int K = out_size;                    // masked count
    (void)M; (void)n_in;

    int nb = (N + CBS - 1) / CBS;        // 782 for N=200000 (< MAX_BLOCKS)

    count_kernel<<<nb, CBS>>>(symbols, N, sym_buf, T);
    scatter_fused_kernel<<<nb, CBS>>>(symbols, N, sym_buf, T);

    int pairs = (K + 1) / 2;             // one warp per node pair
    int warps_per_block = 8;             // 256 threads
    int blocks = (pairs + warps_per_block - 1) / warps_per_block;
    gatherdot_kernel<<<blocks, warps_per_block * 32>>>(
        f00, f01, f10, f11, f20, f21,
        w0, w1, w2, b0, b1, b2,
        meta, (float*)d_out, K, D / 4);
}

// round 12
// speedup vs baseline: 1.3755x; 1.0764x over previous
#include <cuda_runtime.h>

// ---------------- scratch (no allocations allowed) ----------------
#define MAX_K      65536
#define MAX_BLOCKS 4096
#define CBS        256           // compaction block size
#define CNT_FLAG   0x40000000
#define CNT_MASK   0x3FFFFFFF

__device__ int g_idx[MAX_K];     // compacted masked node ids, in node order
__device__ int g_counts[MAX_BLOCKS];

// ---------------- single-pass compaction: count + publish + prefix-spin + scatter ----------------
__global__ void compact_kernel(const int* __restrict__ sym, int N,
                               const int* __restrict__ symbuf, int T) {
    __shared__ int sbuf[8];
    __shared__ int red[CBS / 32];
    __shared__ int warp_off[CBS / 32];
    __shared__ int block_pre;

    int tid = threadIdx.x;
    int b = blockIdx.x;
    if (tid < T && tid < 8) sbuf[tid] = symbuf[tid];
    __syncthreads();

    // ---- mask + ballot ----
    int i = b * CBS + tid;
    bool m = false;
    if (i < N) {
        int s = sym[i];
        #pragma unroll 4
        for (int t = 0; t < T; t++) m |= (s == sbuf[t]);
    }
    unsigned ball = __ballot_sync(0xffffffffu, m);
    int lane = tid & 31, w = tid >> 5;
    if (lane == 0) warp_off[w] = __popc(ball);
    __syncthreads();

    // ---- publish own count (payload inside the atomic word; no extra fence needed) ----
    if (tid == 0) {
        int cnt = 0;
        #pragma unroll
        for (int k = 0; k < CBS / 32; k++) cnt += warp_off[k];
        atomicExch(&g_counts[b], cnt | CNT_FLAG);
    }

    // ---- exclusive prefix over predecessor blocks (spin until each is published) ----
    // All blocks are resident simultaneously (grid < concurrent capacity), so spinning is safe.
    int pre = 0;
    for (int j = tid; j < b; j += CBS) {
        int v;
        do { v = atomicAdd(&g_counts[j], 0); } while (!(v & CNT_FLAG));
        pre += v & CNT_MASK;
    }
    #pragma unroll
    for (int o = 16; o; o >>= 1) pre += __shfl_down_sync(0xffffffffu, pre, o);
    if (lane == 0) red[w] = pre;
    __syncthreads();
    if (tid == 0) {
        int s = 0;
        #pragma unroll
        for (int k = 0; k < CBS / 32; k++) s += red[k];
        block_pre = s;
        // convert warp counts to intra-block exclusive offsets
        int acc = 0;
        #pragma unroll
        for (int k = 0; k < CBS / 32; k++) { int c = warp_off[k]; warp_off[k] = acc; acc += c; }
    }
    __syncthreads();

    // ---- ordered scatter ----
    if (m) {
        int pos = block_pre + warp_off[w] + __popc(ball & ((1u << lane) - 1u));
        g_idx[pos] = i;
    }
}

// ---------------- main: warp-per-masked-node gather-dot (R4, at roofline — FROZEN) ----------------
__device__ __forceinline__ float dot4(float4 a, float4 b) {
    return a.x * b.x + a.y * b.y + a.z * b.z + a.w * b.w;
}

__global__ void __launch_bounds__(256, 8) gatherdot_kernel(
    const float* __restrict__ f00, const float* __restrict__ f01,
    const float* __restrict__ f10, const float* __restrict__ f11,
    const float* __restrict__ f20, const float* __restrict__ f21,
    const float* __restrict__ w0, const float* __restrict__ w1,
    const float* __restrict__ w2,
    const float* __restrict__ b0, const float* __restrict__ b1,
    const float* __restrict__ b2,
    const int* __restrict__ meta,
    float* __restrict__ out, int K, int d4)
{
    int gw = (blockIdx.x * blockDim.x + threadIdx.x) >> 5;
    if (gw >= K) return;
    int lane = threadIdx.x & 31;

    int i = g_idx[gw];
    int mid = meta[i];

    size_t fo = (size_t)i * (size_t)d4;
    size_t wo = (size_t)mid * (size_t)d4;

    // independent bias loads issued early (L2-resident, tiny)
    float bias = 2.0f * (b0[mid] + b1[mid] + b2[mid]);

    float acc = 0.0f;

    #pragma unroll 3
    for (int p = 0; p < 3; p++) {
        const float4* W;
        const float4* Fa;
        const float4* Fb;
        if (p == 0)      { W = (const float4*)w0; Fa = (const float4*)f00; Fb = (const float4*)f01; }
        else if (p == 1) { W = (const float4*)w1; Fa = (const float4*)f10; Fb = (const float4*)f11; }
        else             { W = (const float4*)w2; Fa = (const float4*)f20; Fb = (const float4*)f21; }

        #pragma unroll 2
        for (int c = lane; c < d4; c += 32) {
            float4 a  = W[wo + c];               // L2-cached (heavy reuse across nodes)
            float4 x0 = __ldcs(&Fa[fo + c]);     // streamed, no reuse
            float4 x1 = __ldcs(&Fb[fo + c]);
            acc += dot4(x0, a) + dot4(x1, a);
        }
    }

    // warp reduction
    #pragma unroll
    for (int off = 16; off; off >>= 1)
        acc += __shfl_down_sync(0xffffffffu, acc, off);

    if (lane == 0) {
        out[gw] = (acc + bias) * (1.0f / 6.0f);
    }
}

// ---------------- launcher ----------------
extern "C" void kernel_launch(void* const* d_in, const int* in_sizes, int n_in,
                              void* d_out, int out_size) {
    const float* f00 = (const float*)d_in[0];
    const float* f01 = (const float*)d_in[1];
    const float* f10 = (const float*)d_in[2];
    const float* f11 = (const float*)d_in[3];
    const float* f20 = (const float*)d_in[4];
    const float* f21 = (const float*)d_in[5];
    const float* w0  = (const float*)d_in[6];
    const float* w1  = (const float*)d_in[7];
    const float* w2  = (const float*)d_in[8];
    const float* b0  = (const float*)d_in[9];
    const float* b1  = (const float*)d_in[10];
    const float* b2  = (const float*)d_in[11];
    const int* symbols = (const int*)d_in[12];
    const int* meta    = (const int*)d_in[13];
    const int* sym_buf = (const int*)d_in[14];

    int M = in_sizes[9];                 // b0 has M elements
    int D = in_sizes[6] / M;             // w0 has M*D
    int N = in_sizes[0] / D;             // feat00 has N*D
    int T = in_sizes[14];                // sym_buf length
    int K = out_size;                    // masked count
    (void)M; (void)n_in;

    int nb = (N + CBS - 1) / CBS;        // 782 for N=200000 — fits resident (<1184 blocks)

    compact_kernel<<<nb, CBS>>>(symbols, N, sym_buf, T);

    int warps_per_block = 8;             // 256 threads
    int blocks = (K + warps_per_block - 1) / warps_per_block;
    gatherdot_kernel<<<blocks, warps_per_block * 32>>>(
        f00, f01, f10, f11, f20, f21,
        w0, w1, w2, b0, b1, b2,
        meta, (float*)d_out, K, D / 4);
}

// round 15
// speedup vs baseline: 1.4765x; 1.0734x over previous
#include <cuda_runtime.h>

// ---------------- scratch (no allocations allowed) ----------------
#define MAX_K      65536
#define MAX_BLOCKS 4096
#define CBS        256            // threads per compaction block
#define NPT        4              // nodes per thread (int4)
#define NPB        (CBS * NPT)    // nodes per block = 1024

__device__ int g_idx[MAX_K];      // compacted masked node ids, in node order
__device__ int g_counts[MAX_BLOCKS];

// ---------------- helpers ----------------
__device__ __forceinline__ unsigned mask4(const int* __restrict__ sym, int base, int N,
                                          const int* sbuf, int T) {
    unsigned mm = 0;
    if (base + NPT <= N) {
        int4 v = *reinterpret_cast<const int4*>(sym + base);   // N%4==0, base%4==0
        #pragma unroll 4
        for (int t = 0; t < T; t++) {
            mm |= (v.x == sbuf[t]) ? 1u : 0u;
            mm |= (v.y == sbuf[t]) ? 2u : 0u;
            mm |= (v.z == sbuf[t]) ? 4u : 0u;
            mm |= (v.w == sbuf[t]) ? 8u : 0u;
        }
    } else {
        for (int e = 0; e < NPT; e++) {
            int i = base + e;
            if (i < N) {
                int s = sym[i];
                for (int t = 0; t < T; t++)
                    if (s == sbuf[t]) { mm |= (1u << e); break; }
            }
        }
    }
    return mm;
}

// ---------------- pass 1: per-block masked count (4 nodes/thread) ----------------
__global__ void count_kernel(const int* __restrict__ sym, int N,
                             const int* __restrict__ symbuf, int T) {
    __shared__ int sbuf[8];
    __shared__ int warp_cnt[CBS / 32];
    int tid = threadIdx.x;
    if (tid < T && tid < 8) sbuf[tid] = symbuf[tid];
    __syncthreads();

    int base = blockIdx.x * NPB + tid * NPT;
    unsigned mm = mask4(sym, base, N, sbuf, T);
    int cnt = __popc(mm);

    #pragma unroll
    for (int o = 16; o; o >>= 1) cnt += __shfl_down_sync(0xffffffffu, cnt, o);
    if ((tid & 31) == 0) warp_cnt[tid >> 5] = cnt;
    __syncthreads();
    if (tid == 0) {
        int c = 0;
        #pragma unroll
        for (int k = 0; k < CBS / 32; k++) c += warp_cnt[k];
        g_counts[blockIdx.x] = c;
    }
}

// ---------------- pass 2: prefix recompute + ordered scatter (4 nodes/thread) ----------------
__global__ void scatter_kernel(const int* __restrict__ sym, int N,
                               const int* __restrict__ symbuf, int T) {
    __shared__ int sbuf[8];
    __shared__ int red[CBS / 32];
    __shared__ int warp_base[CBS / 32];
    __shared__ int block_pre;

    int tid = threadIdx.x;
    int b = blockIdx.x;
    if (tid < T && tid < 8) sbuf[tid] = symbuf[tid];
    __syncthreads();

    // exclusive prefix over predecessor blocks (<=195 entries: one per thread)
    int pre = (tid < b) ? g_counts[tid] : 0;
    #pragma unroll
    for (int o = 16; o; o >>= 1) pre += __shfl_down_sync(0xffffffffu, pre, o);
    if ((tid & 31) == 0) red[tid >> 5] = pre;
    __syncthreads();
    if (tid == 0) {
        int s = 0;
        #pragma unroll
        for (int k = 0; k < CBS / 32; k++) s += red[k];
        block_pre = s;
    }

    // per-thread mask + count
    int base = b * NPB + tid * NPT;
    unsigned mm = mask4(sym, base, N, sbuf, T);
    int cnt = __popc(mm);

    // warp-level exclusive scan of per-thread counts (order-preserving)
    int lane = tid & 31, w = tid >> 5;
    int incl = cnt;
    #pragma unroll
    for (int o = 1; o < 32; o <<= 1) {
        int x = __shfl_up_sync(0xffffffffu, incl, o);
        if (lane >= o) incl += x;
    }
    int excl = incl - cnt;
    int wtot = __shfl_sync(0xffffffffu, incl, 31);
    if (lane == 31) warp_base[w] = wtot;   // store warp totals
    __syncthreads();
    if (tid == 0) {
        int acc = 0;
        #pragma unroll
        for (int k = 0; k < CBS / 32; k++) { int c = warp_base[k]; warp_base[k] = acc; acc += c; }
    }
    __syncthreads();

    int pos = block_pre + warp_base[w] + excl;
    #pragma unroll
    for (int e = 0; e < NPT; e++) {
        if (mm & (1u << e)) g_idx[pos++] = base + e;
    }
}

// ---------------- main: warp-per-masked-node gather-dot (FROZEN at roofline) ----------------
__device__ __forceinline__ float dot4(float4 a, float4 b) {
    return a.x * b.x + a.y * b.y + a.z * b.z + a.w * b.w;
}

__global__ void __launch_bounds__(256, 8) gatherdot_kernel(
    const float* __restrict__ f00, const float* __restrict__ f01,
    const float* __restrict__ f10, const float* __restrict__ f11,
    const float* __restrict__ f20, const float* __restrict__ f21,
    const float* __restrict__ w0, const float* __restrict__ w1,
    const float* __restrict__ w2,
    const float* __restrict__ b0, const float* __restrict__ b1,
    const float* __restrict__ b2,
    const int* __restrict__ meta,
    float* __restrict__ out, int K, int d4)
{
    int gw = (blockIdx.x * blockDim.x + threadIdx.x) >> 5;
    if (gw >= K) return;
    int lane = threadIdx.x & 31;

    int i = g_idx[gw];
    int mid = meta[i];

    size_t fo = (size_t)i * (size_t)d4;
    size_t wo = (size_t)mid * (size_t)d4;

    // independent bias loads issued early (L2-resident, tiny)
    float bias = 2.0f * (b0[mid] + b1[mid] + b2[mid]);

    float acc = 0.0f;

    #pragma unroll 3
    for (int p = 0; p < 3; p++) {
        const float4* W;
        const float4* Fa;
        const float4* Fb;
        if (p == 0)      { W = (const float4*)w0; Fa = (const float4*)f00; Fb = (const float4*)f01; }
        else if (p == 1) { W = (const float4*)w1; Fa = (const float4*)f10; Fb = (const float4*)f11; }
        else             { W = (const float4*)w2; Fa = (const float4*)f20; Fb = (const float4*)f21; }

        #pragma unroll 2
        for (int c = lane; c < d4; c += 32) {
            float4 a  = W[wo + c];               // L2-cached (heavy reuse across nodes)
            float4 x0 = __ldcs(&Fa[fo + c]);     // streamed, no reuse
            float4 x1 = __ldcs(&Fb[fo + c]);
            acc += dot4(x0, a) + dot4(x1, a);
        }
    }

    // warp reduction
    #pragma unroll
    for (int off = 16; off; off >>= 1)
        acc += __shfl_down_sync(0xffffffffu, acc, off);

    if (lane == 0) {
        out[gw] = (acc + bias) * (1.0f / 6.0f);
    }
}

// ---------------- launcher ----------------
extern "C" void kernel_launch(void* const* d_in, const int* in_sizes, int n_in,
                              void* d_out, int out_size) {
    const float* f00 = (const float*)d_in[0];
    const float* f01 = (const float*)d_in[1];
    const float* f10 = (const float*)d_in[2];
    const float* f11 = (const float*)d_in[3];
    const float* f20 = (const float*)d_in[4];
    const float* f21 = (const float*)d_in[5];
    const float* w0  = (const float*)d_in[6];
    const float* w1  = (const float*)d_in[7];
    const float* w2  = (const float*)d_in[8];
    const float* b0  = (const float*)d_in[9];
    const float* b1  = (const float*)d_in[10];
    const float* b2  = (const float*)d_in[11];
    const int* symbols = (const int*)d_in[12];
    const int* meta    = (const int*)d_in[13];
    const int* sym_buf = (const int*)d_in[14];

    int M = in_sizes[9];                 // b0 has M elements
    int D = in_sizes[6] / M;             // w0 has M*D
    int N = in_sizes[0] / D;             // feat00 has N*D
    int T = in_sizes[14];                // sym_buf length
    int K = out_size;                    // masked count
    (void)M; (void)n_in;

    int nb = (N + NPB - 1) / NPB;        // 196 for N=200000 (fits one 256-thread prefix)

    count_kernel<<<nb, CBS>>>(symbols, N, sym_buf, T);
    scatter_kernel<<<nb, CBS>>>(symbols, N, sym_buf, T);

    int warps_per_block = 8;             // 256 threads
    int blocks = (K + warps_per_block - 1) / warps_per_block;
    gatherdot_kernel<<<blocks, warps_per_block * 32>>>(
        f00, f01, f10, f11, f20, f21,
        w0, w1, w2, b0, b1, b2,
        meta, (float*)d_out, K, D / 4);
}